// round 2
// baseline (speedup 1.0000x reference)
#include <cuda_runtime.h>
#include <math.h>

// Problem constants: x[8, 2048, 1024], W[1024,1024]
#define B_ 8
#define T_ 2048
#define C_ 1024
#define K_ 1024

#define PI_F   3.14159265358979323846f
#define STEP_F 1.04719755119659774615f   // pi/3, rounded to f32
#define TOL_F  0.15f

// Intermediate: (angle, amp) per element, [B,T,C] layout. 128 MB static device buffer.
__device__ float2 g_pack[(size_t)B_ * T_ * C_];

// ---------------- packed f32x2 helpers ----------------
__device__ __forceinline__ void ffma2(unsigned long long& d,
                                      unsigned long long a,
                                      unsigned long long b) {
    asm("fma.rn.f32x2 %0, %1, %2, %0;" : "+l"(d) : "l"(a), "l"(b));
}
__device__ __forceinline__ unsigned long long pack2(float x, float y) {
    unsigned long long r;
    asm("mov.b64 %0, {%1, %2};" : "=l"(r) : "f"(x), "f"(y));
    return r;
}
__device__ __forceinline__ void unpack2(unsigned long long v, float& x, float& y) {
    asm("mov.b64 {%0, %1}, %2;" : "=f"(x), "=f"(y) : "l"(v));
}

// ---------------- fused dual GEMM + epilogue ----------------
// out tile 128(M) x 128(N); each CTA computes BOTH phi and amp projections for
// its tile (shared x tile), then writes packed (angle, amp) float2.
#define BM 128
#define BN 128
#define BK 16
#define TM 8
#define TN 8
#define NTHREADS 256

__global__ void __launch_bounds__(NTHREADS, 1)
fused_gemm_kernel(const float* __restrict__ x,
                  const float* __restrict__ Wp,
                  const float* __restrict__ bph,
                  const float* __restrict__ Wa,
                  const float* __restrict__ bam)
{
    __shared__ float As[BK][BM];
    __shared__ float Bp[BK][BN];
    __shared__ float Ba[BK][BN];

    const int tid  = threadIdx.x;
    const int row0 = blockIdx.y * BM;   // over B*T = 16384
    const int col0 = blockIdx.x * BN;   // over D = 1024

    const float* Ag  = x  + (size_t)row0 * K_;
    const float* Bpg = Wp + (size_t)col0 * K_;
    const float* Bag = Wa + (size_t)col0 * K_;

    const int lr = tid >> 2;        // 0..63
    const int lc = (tid & 3) * 4;   // 0,4,8,12  (k offset within BK)

    const int m0 = (tid >> 4) * TM; // 0..120
    const int n0 = (tid & 15) * TN; // 0..120

    // packed accumulators: [TM][TN/2] pairs for each projection
    unsigned long long accP[TM][TN / 2];
    unsigned long long accA[TM][TN / 2];
#pragma unroll
    for (int i = 0; i < TM; i++)
#pragma unroll
        for (int j = 0; j < TN / 2; j++) { accP[i][j] = 0ULL; accA[i][j] = 0ULL; }

    for (int kt = 0; kt < K_; kt += BK) {
        // stage tiles: each thread loads 2 float4 per operand
#pragma unroll
        for (int i = 0; i < 2; i++) {
            int r = lr + i * 64;
            float4 av = *(const float4*)&Ag [(size_t)r * K_ + kt + lc];
            As[lc + 0][r] = av.x; As[lc + 1][r] = av.y;
            As[lc + 2][r] = av.z; As[lc + 3][r] = av.w;
            float4 pv = *(const float4*)&Bpg[(size_t)r * K_ + kt + lc];
            Bp[lc + 0][r] = pv.x; Bp[lc + 1][r] = pv.y;
            Bp[lc + 2][r] = pv.z; Bp[lc + 3][r] = pv.w;
            float4 qv = *(const float4*)&Bag[(size_t)r * K_ + kt + lc];
            Ba[lc + 0][r] = qv.x; Ba[lc + 1][r] = qv.y;
            Ba[lc + 2][r] = qv.z; Ba[lc + 3][r] = qv.w;
        }
        __syncthreads();

#pragma unroll
        for (int k = 0; k < BK; k++) {
            float4 a04 = *(const float4*)&As[k][m0];
            float4 a44 = *(const float4*)&As[k][m0 + 4];
            float a[TM] = {a04.x, a04.y, a04.z, a04.w, a44.x, a44.y, a44.z, a44.w};

            ulonglong2 bp0 = *(const ulonglong2*)&Bp[k][n0];
            ulonglong2 bp1 = *(const ulonglong2*)&Bp[k][n0 + 4];
            ulonglong2 ba0 = *(const ulonglong2*)&Ba[k][n0];
            ulonglong2 ba1 = *(const ulonglong2*)&Ba[k][n0 + 4];
            unsigned long long bpk[4] = {bp0.x, bp0.y, bp1.x, bp1.y};
            unsigned long long bak[4] = {ba0.x, ba0.y, ba1.x, ba1.y};

#pragma unroll
            for (int i = 0; i < TM; i++) {
                unsigned long long a2 = pack2(a[i], a[i]);
#pragma unroll
                for (int jp = 0; jp < TN / 2; jp++) {
                    ffma2(accP[i][jp], a2, bpk[jp]);
                    ffma2(accA[i][jp], a2, bak[jp]);
                }
            }
        }
        __syncthreads();
    }

    // epilogue: bias + tanh*pi + tesla gate (angle), sigmoid (amp); packed store
#pragma unroll
    for (int i = 0; i < TM; i++) {
        size_t row = (size_t)(row0 + m0 + i);
        float2* dst = &g_pack[row * C_ + col0 + n0];
#pragma unroll
        for (int jp = 0; jp < TN / 2; jp++) {
            float y0, y1, z0, z1;
            unpack2(accP[i][jp], y0, y1);
            unpack2(accA[i][jp], z0, z1);
#pragma unroll
            for (int e = 0; e < 2; e++) {
                int d = col0 + n0 + jp * 2 + e;
                float yp = (e == 0 ? y0 : y1) + bph[d];
                float ya = (e == 0 ? z0 : z1) + bam[d];

                float raw     = tanhf(yp) * PI_F;
                float nearest = rintf(raw / STEP_F) * STEP_F;
                float ang     = (fabsf(raw - nearest) < TOL_F) ? nearest : raw;
                float amp     = 1.0f / (1.0f + expf(-ya));

                dst[jp * 2 + e] = make_float2(ang, amp);
            }
        }
    }
}

// ---------------- sequential scan over T ----------------
// 8192 independent lanes (b,c). 128 CTAs x 64 threads.
// Double-buffered register prefetch of (angle, amp) float2 stream.
#define SCAN_U 8

__global__ void __launch_bounds__(64, 1)
scan_kernel(const float* __restrict__ state,
            float* __restrict__ out,
            float* __restrict__ fstate,
            int write_fstate)
{
    const int b = blockIdx.x >> 4;                        // 8 batches
    const int c = ((blockIdx.x & 15) << 6) + threadIdx.x; // 16 blocks * 64

    const float2* src = g_pack + (size_t)b * T_ * C_ + c;
    float*        op  = out    + (size_t)b * T_ * C_ + c;

    float s = state[b * C_ + c];

    float2 buf[2][SCAN_U];
#pragma unroll
    for (int u = 0; u < SCAN_U; u++) buf[0][u] = src[(size_t)u * C_];

    const int NCH = T_ / SCAN_U;
    for (int ch = 0; ch < NCH; ch++) {
        const int cur = ch & 1, nxt = cur ^ 1;
        if (ch + 1 < NCH) {
#pragma unroll
            for (int u = 0; u < SCAN_U; u++)
                buf[nxt][u] = src[(size_t)((ch + 1) * SCAN_U + u) * C_];
        }
#pragma unroll
        for (int u = 0; u < SCAN_U; u++) {
            float2 pa = buf[cur][u];
            float sn, cs;
            sincosf(pa.x, &sn, &cs);   // accurate variant; off the serial chain
            // match reference arithmetic: clip(cos*s - sin*(1-s), -1, 1)
            float ns = cs * s - sn * (1.0f - s);
            ns = fminf(1.0f, fmaxf(-1.0f, ns));
            op[(size_t)(ch * SCAN_U + u) * C_] = pa.y * ns;
            s = ns;
        }
    }
    if (write_fstate) fstate[b * C_ + c] = s;
}

// ---------------- launch ----------------
extern "C" void kernel_launch(void* const* d_in, const int* in_sizes, int n_in,
                              void* d_out, int out_size)
{
    const float* x     = (const float*)d_in[0];
    const float* state = (const float*)d_in[1];
    const float* Wp    = (const float*)d_in[2];
    const float* bp    = (const float*)d_in[3];
    const float* Wa    = (const float*)d_in[4];
    const float* ba    = (const float*)d_in[5];

    float* out = (float*)d_out;
    const long long total = (long long)B_ * T_ * C_;   // 16,777,216
    const int write_fs = (out_size >= total + B_ * C_);
    float* fs = out + total;

    dim3 grid(C_ / BN, (B_ * T_) / BM);   // (8, 128)
    fused_gemm_kernel<<<grid, NTHREADS>>>(x, Wp, bp, Wa, ba);
    scan_kernel<<<B_ * 16, 64>>>(state, out, fs, write_fs);
}

// round 3
// speedup vs baseline: 1.1894x; 1.1894x over previous
#include <cuda_runtime.h>
#include <math.h>

// Problem constants: x[8, 2048, 1024], W[1024,1024]
#define B_ 8
#define T_ 2048
#define C_ 1024
#define K_ 1024

#define PI_F   3.14159265358979323846f
#define STEP_F 1.04719755119659774615f   // pi/3, rounded to f32
#define TOL_F  0.15f

// Intermediate: (angle, amp) per element, [B,T,C] layout. 128 MB static device buffer.
__device__ float2 g_pack[(size_t)B_ * T_ * C_];

// ---------------- packed f32x2 helpers ----------------
__device__ __forceinline__ void ffma2(unsigned long long& d,
                                      unsigned long long a,
                                      unsigned long long b) {
    asm("fma.rn.f32x2 %0, %1, %2, %0;" : "+l"(d) : "l"(a), "l"(b));
}
__device__ __forceinline__ unsigned long long pack2(float x, float y) {
    unsigned long long r;
    asm("mov.b64 %0, {%1, %2};" : "=l"(r) : "f"(x), "f"(y));
    return r;
}
__device__ __forceinline__ void unpack2(unsigned long long v, float& x, float& y) {
    asm("mov.b64 {%0, %1}, %2;" : "=f"(x), "=f"(y) : "l"(v));
}

// ---------------- fused dual GEMM + epilogue ----------------
// out tile 128(M) x 128(N); each CTA computes BOTH phi and amp projections for
// its tile (shared x tile). 2-stage register-staged double buffering:
// gmem->reg prefetch for stage k+1 overlaps compute on stage k.
#define BM 128
#define BN 128
#define BK 8
#define TM 8
#define TN 8
#define NTHREADS 256
#define PAD 4
#define NK (K_ / BK)   // 128 stages

__global__ void __launch_bounds__(NTHREADS, 1)
fused_gemm_kernel(const float* __restrict__ x,
                  const float* __restrict__ Wp,
                  const float* __restrict__ bph,
                  const float* __restrict__ Wa,
                  const float* __restrict__ bam)
{
    __shared__ float As[2][BK][BM + PAD];
    __shared__ float Bs[2][BK][BN + PAD];
    __shared__ float Cs[2][BK][BN + PAD];

    const int tid  = threadIdx.x;
    const int row0 = blockIdx.y * BM;   // over B*T = 16384
    const int col0 = blockIdx.x * BN;   // over D = 1024

    // staging map: 128 rows x 8 cols per operand tile; 2 float4 per row;
    // 256 chunks -> 1 chunk/thread. r = tid>>1, lc = (tid&1)*4.
    const int r  = tid >> 1;
    const int lc = (tid & 1) * 4;

    const float* Ag = x  + (size_t)(row0 + r) * K_ + lc;
    const float* Pg = Wp + (size_t)(col0 + r) * K_ + lc;
    const float* Qg = Wa + (size_t)(col0 + r) * K_ + lc;

    const int m0 = (tid >> 4) * TM; // 0..120
    const int n0 = (tid & 15) * TN; // 0..120

    unsigned long long accP[TM][TN / 2];
    unsigned long long accA[TM][TN / 2];
#pragma unroll
    for (int i = 0; i < TM; i++)
#pragma unroll
        for (int j = 0; j < TN / 2; j++) { accP[i][j] = 0ULL; accA[i][j] = 0ULL; }

    // prologue: stage 0
    float4 rA = *(const float4*)Ag;
    float4 rP = *(const float4*)Pg;
    float4 rQ = *(const float4*)Qg;
#pragma unroll
    for (int j = 0; j < 4; j++) {
        As[0][lc + j][r] = ((const float*)&rA)[j];
        Bs[0][lc + j][r] = ((const float*)&rP)[j];
        Cs[0][lc + j][r] = ((const float*)&rQ)[j];
    }
    __syncthreads();

    for (int kt = 0; kt < NK; kt++) {
        const int cur = kt & 1;

        // prefetch next stage into registers (overlaps with compute below)
        if (kt + 1 < NK) {
            const int off = (kt + 1) * BK;
            rA = *(const float4*)(Ag + off);
            rP = *(const float4*)(Pg + off);
            rQ = *(const float4*)(Qg + off);
        }

#pragma unroll
        for (int k = 0; k < BK; k++) {
            float4 a04 = *(const float4*)&As[cur][k][m0];
            float4 a44 = *(const float4*)&As[cur][k][m0 + 4];
            float a[TM] = {a04.x, a04.y, a04.z, a04.w, a44.x, a44.y, a44.z, a44.w};

            ulonglong2 bp0 = *(const ulonglong2*)&Bs[cur][k][n0];
            ulonglong2 bp1 = *(const ulonglong2*)&Bs[cur][k][n0 + 4];
            ulonglong2 ba0 = *(const ulonglong2*)&Cs[cur][k][n0];
            ulonglong2 ba1 = *(const ulonglong2*)&Cs[cur][k][n0 + 4];
            unsigned long long bpk[4] = {bp0.x, bp0.y, bp1.x, bp1.y};
            unsigned long long bak[4] = {ba0.x, ba0.y, ba1.x, ba1.y};

#pragma unroll
            for (int i = 0; i < TM; i++) {
                unsigned long long a2 = pack2(a[i], a[i]);
#pragma unroll
                for (int jp = 0; jp < TN / 2; jp++) {
                    ffma2(accP[i][jp], a2, bpk[jp]);
                    ffma2(accA[i][jp], a2, bak[jp]);
                }
            }
        }

        __syncthreads();   // everyone done reading buffer (cur^1 from prev iter is free)
        if (kt + 1 < NK) {
            const int nxt = cur ^ 1;
#pragma unroll
            for (int j = 0; j < 4; j++) {
                As[nxt][lc + j][r] = ((const float*)&rA)[j];
                Bs[nxt][lc + j][r] = ((const float*)&rP)[j];
                Cs[nxt][lc + j][r] = ((const float*)&rQ)[j];
            }
            __syncthreads();   // stores visible before next compute
        }
    }

    // epilogue: bias + tanh*pi + tesla gate (angle), sigmoid (amp); packed store
#pragma unroll
    for (int i = 0; i < TM; i++) {
        size_t row = (size_t)(row0 + m0 + i);
        float2* dst = &g_pack[row * C_ + col0 + n0];
#pragma unroll
        for (int jp = 0; jp < TN / 2; jp++) {
            float y0, y1, z0, z1;
            unpack2(accP[i][jp], y0, y1);
            unpack2(accA[i][jp], z0, z1);
#pragma unroll
            for (int e = 0; e < 2; e++) {
                int d = col0 + n0 + jp * 2 + e;
                float yp = (e == 0 ? y0 : y1) + bph[d];
                float ya = (e == 0 ? z0 : z1) + bam[d];

                float raw     = tanhf(yp) * PI_F;
                float nearest = rintf(raw / STEP_F) * STEP_F;
                float ang     = (fabsf(raw - nearest) < TOL_F) ? nearest : raw;
                float amp     = 1.0f / (1.0f + expf(-ya));

                dst[jp * 2 + e] = make_float2(ang, amp);
            }
        }
    }
}

// ---------------- sequential scan over T ----------------
// 8192 independent lanes (b,c). 128 CTAs x 64 threads.
// Deep (16-wide) double-buffered register prefetch; MUFU sincos.
#define SCAN_U 16

__global__ void __launch_bounds__(64, 1)
scan_kernel(const float* __restrict__ state,
            float* __restrict__ out,
            float* __restrict__ fstate,
            int write_fstate)
{
    const int b = blockIdx.x >> 4;                        // 8 batches
    const int c = ((blockIdx.x & 15) << 6) + threadIdx.x; // 16 blocks * 64

    const float2* src = g_pack + (size_t)b * T_ * C_ + c;
    float*        op  = out    + (size_t)b * T_ * C_ + c;

    float s = state[b * C_ + c];

    float2 buf[2][SCAN_U];
#pragma unroll
    for (int u = 0; u < SCAN_U; u++) buf[0][u] = src[(size_t)u * C_];

    const int NCH = T_ / SCAN_U;   // 128
    for (int ch = 0; ch < NCH; ch++) {
        const int cur = ch & 1, nxt = cur ^ 1;
        if (ch + 1 < NCH) {
#pragma unroll
            for (int u = 0; u < SCAN_U; u++)
                buf[nxt][u] = src[(size_t)((ch + 1) * SCAN_U + u) * C_];
        }
#pragma unroll
        for (int u = 0; u < SCAN_U; u++) {
            float2 pa = buf[cur][u];
            float sn, cs;
            __sincosf(pa.x, &sn, &cs);           // MUFU; |x|<=pi -> ~3e-7 abs err
            // clip(cos*s - sin*(1-s)) = clip((cos+sin)*s - sin)
            float ns = fmaf(cs + sn, s, -sn);
            ns = fminf(1.0f, fmaxf(-1.0f, ns));
            op[(size_t)(ch * SCAN_U + u) * C_] = pa.y * ns;
            s = ns;
        }
    }
    if (write_fstate) fstate[b * C_ + c] = s;
}

// ---------------- launch ----------------
extern "C" void kernel_launch(void* const* d_in, const int* in_sizes, int n_in,
                              void* d_out, int out_size)
{
    const float* x     = (const float*)d_in[0];
    const float* state = (const float*)d_in[1];
    const float* Wp    = (const float*)d_in[2];
    const float* bp    = (const float*)d_in[3];
    const float* Wa    = (const float*)d_in[4];
    const float* ba    = (const float*)d_in[5];

    float* out = (float*)d_out;
    const long long total = (long long)B_ * T_ * C_;   // 16,777,216
    const int write_fs = (out_size >= total + B_ * C_);
    float* fs = out + total;

    dim3 grid(C_ / BN, (B_ * T_) / BM);   // (8, 128)
    fused_gemm_kernel<<<grid, NTHREADS>>>(x, Wp, bp, Wa, ba);
    scan_kernel<<<B_ * 16, 64>>>(state, out, fs, write_fs);
}